// round 1
// baseline (speedup 1.0000x reference)
#include <cuda_runtime.h>
#include <math.h>

#define BATCH  2048
#define NROWS  512
#define MDIM   64
#define HDIM   100
#define INDIM  64
#define OUTDIM 64
#define EPS    1e-8f

#define SCR_STRIDE 288   // per-batch scratch floats (272 used, padded)
__device__ float g_scratch[(size_t)BATCH * SCR_STRIDE];

__device__ __forceinline__ float softplus_f(float x) {
    return (x > 20.f) ? x : log1pf(expf(x));
}
__device__ __forceinline__ float sigmoid_f(float x) {
    return 1.f / (1.f + expf(-x));
}

// ---------------------------------------------------------------------------
// Kernel A: per-batch head parameters.
//   h = x@cW+cb ; p_w = h@whW+whb ; p_r = h@rhW+rhb ; we = h@weW+web
//   scratch layout per batch: [0:64) k_w, [64:128) k_r, [128:192) e=sigmoid,
//   [192:256) a, [256..269] scalars:
//   beta_w,gate_w,sh_w0..2,gamma_w,kn_w, beta_r,gate_r,sh_r0..2,gamma_r,kn_r
// ---------------------------------------------------------------------------
__global__ __launch_bounds__(256) void ntm_params_kernel(
    const float* __restrict__ x,  const float* __restrict__ cW,  const float* __restrict__ cb,
    const float* __restrict__ whW, const float* __restrict__ whb,
    const float* __restrict__ weW, const float* __restrict__ web,
    const float* __restrict__ rhW, const float* __restrict__ rhb)
{
    const int TB = 64;
    extern __shared__ float sm[];
    float* xs  = sm;                    // 64*64
    float* hs  = xs  + TB * INDIM;      // 64*100
    float* pws = hs  + TB * HDIM;       // 64*70
    float* prs = pws + TB * 70;         // 64*70

    const int tid = threadIdx.x;
    const int b0  = blockIdx.x * TB;

    for (int i = tid; i < TB * INDIM; i += 256) xs[i] = x[(size_t)b0 * INDIM + i];
    __syncthreads();

    // h
    for (int idx = tid; idx < TB * HDIM; idx += 256) {
        int b = idx / HDIM, j = idx % HDIM;
        const float* xr = xs + b * INDIM;
        float acc = cb[j];
        #pragma unroll 8
        for (int i = 0; i < INDIM; i++) acc = fmaf(xr[i], cW[i * HDIM + j], acc);
        hs[idx] = acc;
    }
    __syncthreads();

    // p_w, p_r (fused: same h row)
    for (int idx = tid; idx < TB * 70; idx += 256) {
        int b = idx / 70, j = idx % 70;
        const float* hr = hs + b * HDIM;
        float aw = whb[j], ar = rhb[j];
        #pragma unroll 4
        for (int i = 0; i < HDIM; i++) {
            float hv = hr[i];
            aw = fmaf(hv, whW[i * 70 + j], aw);
            ar = fmaf(hv, rhW[i * 70 + j], ar);
        }
        pws[idx] = aw;  prs[idx] = ar;
    }

    // we -> e (sigmoid), a
    for (int idx = tid; idx < TB * 128; idx += 256) {
        int b = idx / 128, j = idx % 128;
        const float* hr = hs + b * HDIM;
        float acc = web[j];
        #pragma unroll 4
        for (int i = 0; i < HDIM; i++) acc = fmaf(hr[i], weW[i * 128 + j], acc);
        float* scr = g_scratch + (size_t)(b0 + b) * SCR_STRIDE;
        if (j < 64) scr[128 + j]        = sigmoid_f(acc);  // e
        else        scr[192 + (j - 64)] = acc;             // a
    }
    __syncthreads();

    // k vectors (coalesced copy)
    for (int idx = tid; idx < TB * 64; idx += 256) {
        int b = idx >> 6, j = idx & 63;
        float* scr = g_scratch + (size_t)(b0 + b) * SCR_STRIDE;
        scr[j]      = pws[b * 70 + j];
        scr[64 + j] = prs[b * 70 + j];
    }

    // per-batch scalars
    if (tid < TB) {
        int b = tid;
        float* scr = g_scratch + (size_t)(b0 + b) * SCR_STRIDE + 256;
        const float* pw = pws + b * 70;
        const float* pr = prs + b * 70;
        float ssw = 0.f, ssr = 0.f;
        #pragma unroll 8
        for (int j = 0; j < 64; j++) { ssw = fmaf(pw[j], pw[j], ssw); ssr = fmaf(pr[j], pr[j], ssr); }

        scr[0] = softplus_f(pw[64]);           // beta_w
        scr[1] = sigmoid_f(pw[65]);            // gate_w
        float m  = fmaxf(pw[66], fmaxf(pw[67], pw[68]));
        float e0 = expf(pw[66] - m), e1 = expf(pw[67] - m), e2 = expf(pw[68] - m);
        float s  = e0 + e1 + e2;
        scr[2] = e0 / s; scr[3] = e1 / s; scr[4] = e2 / s;
        scr[5] = 1.f + softplus_f(pw[69]);     // gamma_w
        scr[6] = fmaxf(sqrtf(ssw), EPS);       // kn_w

        scr[7] = softplus_f(pr[64]);           // beta_r
        scr[8] = sigmoid_f(pr[65]);            // gate_r
        m  = fmaxf(pr[66], fmaxf(pr[67], pr[68]));
        e0 = expf(pr[66] - m); e1 = expf(pr[67] - m); e2 = expf(pr[68] - m);
        s  = e0 + e1 + e2;
        scr[9] = e0 / s; scr[10] = e1 / s; scr[11] = e2 / s;
        scr[12] = 1.f + softplus_f(pr[69]);    // gamma_r
        scr[13] = fmaxf(sqrtf(ssr), EPS);      // kn_r
    }
}

// ---------------------------------------------------------------------------
// Block reductions over 512 threads (16 warps)
// ---------------------------------------------------------------------------
__device__ __forceinline__ float blockReduceSum512(float v, float* red) {
    #pragma unroll
    for (int o = 16; o > 0; o >>= 1) v += __shfl_xor_sync(0xffffffffu, v, o);
    int warp = threadIdx.x >> 5, lane = threadIdx.x & 31;
    if (lane == 0) red[warp] = v;
    __syncthreads();
    if (threadIdx.x < 32) {
        v = (lane < 16) ? red[lane] : 0.f;
        #pragma unroll
        for (int o = 8; o > 0; o >>= 1) v += __shfl_xor_sync(0xffffffffu, v, o);
        if (lane == 0) red[0] = v;
    }
    __syncthreads();
    float r = red[0];
    __syncthreads();
    return r;
}
__device__ __forceinline__ float blockReduceMax512(float v, float* red) {
    #pragma unroll
    for (int o = 16; o > 0; o >>= 1) v = fmaxf(v, __shfl_xor_sync(0xffffffffu, v, o));
    int warp = threadIdx.x >> 5, lane = threadIdx.x & 31;
    if (lane == 0) red[warp] = v;
    __syncthreads();
    if (threadIdx.x < 32) {
        v = (lane < 16) ? red[lane] : -INFINITY;
        #pragma unroll
        for (int o = 8; o > 0; o >>= 1) v = fmaxf(v, __shfl_xor_sync(0xffffffffu, v, o));
        if (lane == 0) red[0] = v;
    }
    __syncthreads();
    float r = red[0];
    __syncthreads();
    return r;
}

// ---------------------------------------------------------------------------
// Kernel B: one CTA per batch. 512 threads.
// Pass 1 (row/thread, HBM stream): 8 dot-moments per memory row.
// Addressing (write then read head, read head uses closed-form dot2/ss2).
// Pass 2 (column-major, L2-hit stream): mem2 write + S1/S2 column sums.
// Finish: r = S1 - e*S2 + c*a ; out = sigmoid(r@oW+ob).
// ---------------------------------------------------------------------------
__global__ __launch_bounds__(512, 2) void ntm_main_kernel(
    const float* __restrict__ memory, const float* __restrict__ read_attn,
    const float* __restrict__ write_attn, const float* __restrict__ oW,
    const float* __restrict__ ob,
    float* __restrict__ out_out, float* __restrict__ out_mem2,
    float* __restrict__ out_wr,  float* __restrict__ out_ww)
{
    __shared__ float c_kw[64], c_kr[64], c_kre[64], c_e[64], c_e2[64], c_a[64], c_ae[64];
    __shared__ float ww_s[512], wr_s[512], wg_s[512];
    __shared__ float s1p[512], s2p[512];
    __shared__ float red[16];
    __shared__ float scal[16];
    __shared__ float rs[64];
    __shared__ float sc2[2];   // ka = k_r.a, aa = a.a

    const int tid = threadIdx.x;
    const int b   = blockIdx.x;

    {
        const float* scr = g_scratch + (size_t)b * SCR_STRIDE;
        if (tid < 64) {
            float kwv = scr[tid], krv = scr[64 + tid], ev = scr[128 + tid], av = scr[192 + tid];
            c_kw[tid] = kwv;  c_kr[tid] = krv;  c_e[tid] = ev;  c_a[tid] = av;
            c_kre[tid] = krv * ev;  c_e2[tid] = ev * ev;  c_ae[tid] = av * ev;
        } else if (tid < 80) {
            scal[tid - 64] = scr[256 + (tid - 64)];
        }
    }
    __syncthreads();
    if (tid < 32) {
        float ka = c_kr[tid] * c_a[tid] + c_kr[tid + 32] * c_a[tid + 32];
        float aa = c_a[tid]  * c_a[tid] + c_a[tid + 32]  * c_a[tid + 32];
        #pragma unroll
        for (int o = 16; o > 0; o >>= 1) {
            ka += __shfl_xor_sync(0xffffffffu, ka, o);
            aa += __shfl_xor_sync(0xffffffffu, aa, o);
        }
        if (tid == 0) { sc2[0] = ka; sc2[1] = aa; }
    }
    __syncthreads();

    // ---- Pass 1: 8 moments of this thread's memory row -------------------
    const int n = tid;
    float d0 = 0, q0 = 0, d1 = 0, d2 = 0, p1 = 0, p2 = 0, t1 = 0, t2 = 0;
    {
        const float4* rg   = (const float4*)(memory + ((size_t)b * NROWS + n) * MDIM);
        const float4* kw4  = (const float4*)c_kw;
        const float4* kr4  = (const float4*)c_kr;
        const float4* kre4 = (const float4*)c_kre;
        const float4* e4   = (const float4*)c_e;
        const float4* e24  = (const float4*)c_e2;
        const float4* a4   = (const float4*)c_a;
        const float4* ae4  = (const float4*)c_ae;
        #pragma unroll 4
        for (int c = 0; c < 16; c++) {
            float4 v  = rg[c];
            float4 kw = kw4[c], kr = kr4[c], kre = kre4[c];
            float4 ee = e4[c],  e2v = e24[c], av = a4[c], ae = ae4[c];
            {
                float vv = v.x, v2 = vv * vv;
                d0 = fmaf(kw.x,  vv, d0);  d1 = fmaf(kr.x, vv, d1);  d2 = fmaf(kre.x, vv, d2);
                t1 = fmaf(av.x,  vv, t1);  t2 = fmaf(ae.x, vv, t2);
                q0 += v2;  p1 = fmaf(ee.x, v2, p1);  p2 = fmaf(e2v.x, v2, p2);
            }
            {
                float vv = v.y, v2 = vv * vv;
                d0 = fmaf(kw.y,  vv, d0);  d1 = fmaf(kr.y, vv, d1);  d2 = fmaf(kre.y, vv, d2);
                t1 = fmaf(av.y,  vv, t1);  t2 = fmaf(ae.y, vv, t2);
                q0 += v2;  p1 = fmaf(ee.y, v2, p1);  p2 = fmaf(e2v.y, v2, p2);
            }
            {
                float vv = v.z, v2 = vv * vv;
                d0 = fmaf(kw.z,  vv, d0);  d1 = fmaf(kr.z, vv, d1);  d2 = fmaf(kre.z, vv, d2);
                t1 = fmaf(av.z,  vv, t1);  t2 = fmaf(ae.z, vv, t2);
                q0 += v2;  p1 = fmaf(ee.z, v2, p1);  p2 = fmaf(e2v.z, v2, p2);
            }
            {
                float vv = v.w, v2 = vv * vv;
                d0 = fmaf(kw.w,  vv, d0);  d1 = fmaf(kr.w, vv, d1);  d2 = fmaf(kre.w, vv, d2);
                t1 = fmaf(av.w,  vv, t1);  t2 = fmaf(ae.w, vv, t2);
                q0 += v2;  p1 = fmaf(ee.w, v2, p1);  p2 = fmaf(e2v.w, v2, p2);
            }
        }
    }

    const float beta_w = scal[0], gate_w = scal[1], shw0 = scal[2], shw1 = scal[3],
                shw2 = scal[4], gamma_w = scal[5], kn_w = scal[6];
    const float beta_r = scal[7], gate_r = scal[8], shr0 = scal[9], shr1 = scal[10],
                shr2 = scal[11], gamma_r = scal[12], kn_r = scal[13];
    const float ka = sc2[0], aa = sc2[1];

    // ---- Write-head addressing -------------------------------------------
    float mn = fmaxf(sqrtf(q0), EPS);
    float sw = beta_w * d0 / (kn_w * mn);
    float mx  = blockReduceMax512(sw, red);
    float ex  = expf(sw - mx);
    float sum = blockReduceSum512(ex, red);
    float wc  = ex / sum;
    float wgv = gate_w * wc + (1.f - gate_w) * write_attn[(size_t)b * NROWS + n];
    wg_s[n] = wgv;
    __syncthreads();
    float tw  = shw2 * wg_s[(n + 511) & 511] + shw1 * wgv + shw0 * wg_s[(n + 1) & 511];
    float twg = powf(tw, gamma_w);
    float tsum = blockReduceSum512(twg, red);
    float ww = twg / (EPS + tsum);
    ww_s[n] = ww;
    out_ww[(size_t)b * NROWS + n] = ww;

    // ---- Read-head addressing on virtual mem2 -----------------------------
    float dot2 = d1 - ww * d2 + ww * ka;
    float ss2  = q0 - 2.f * ww * p1 + ww * ww * p2
               + 2.f * ww * t1 - 2.f * ww * ww * t2 + ww * ww * aa;
    float mn2 = fmaxf(sqrtf(fmaxf(ss2, 0.f)), EPS);
    float sr  = beta_r * dot2 / (kn_r * mn2);
    mx  = blockReduceMax512(sr, red);
    ex  = expf(sr - mx);
    sum = blockReduceSum512(ex, red);
    wc  = ex / sum;
    float wgv2 = gate_r * wc + (1.f - gate_r) * read_attn[(size_t)b * NROWS + n];
    wg_s[n] = wgv2;
    __syncthreads();
    float tw2  = shr2 * wg_s[(n + 511) & 511] + shr1 * wgv2 + shr0 * wg_s[(n + 1) & 511];
    float twg2 = powf(tw2, gamma_r);
    float tsum2 = blockReduceSum512(twg2, red);
    float wr = twg2 / (EPS + tsum2);
    wr_s[n] = wr;
    out_wr[(size_t)b * NROWS + n] = wr;

    float cwr = blockReduceSum512(wr * ww, red);   // sum_n w_r*w_w  (also syncs ww_s/wr_s)

    // ---- Pass 2: column-major mem2 write + S1/S2 --------------------------
    {
        const int m = tid & 63, g = tid >> 6;               // 8 groups x 64 rows
        const float em = c_e[m], am = c_a[m];
        const float* memb = memory   + (size_t)b * NROWS * MDIM;
        float*       m2b  = out_mem2 + (size_t)b * NROWS * MDIM;
        float s1 = 0.f, s2 = 0.f;
        #pragma unroll 4
        for (int i = 0; i < 64; i++) {
            int nn = (g << 6) + i;
            float wwn = ww_s[nn], wrn = wr_s[nn];
            float v = memb[nn * 64 + m];
            float m2 = fmaf(v, 1.f - wwn * em, wwn * am);
            m2b[nn * 64 + m] = m2;
            s1 = fmaf(wrn, v, s1);
            s2 = fmaf(wrn * wwn, v, s2);
        }
        s1p[tid] = s1;  s2p[tid] = s2;
    }
    __syncthreads();

    if (tid < 64) {
        float r1 = 0.f, r2 = 0.f;
        #pragma unroll
        for (int g = 0; g < 8; g++) { r1 += s1p[g * 64 + tid]; r2 += s2p[g * 64 + tid]; }
        rs[tid] = r1 - c_e[tid] * r2 + cwr * c_a[tid];
    }
    __syncthreads();

    if (tid < 64) {
        float acc = ob[tid];
        #pragma unroll 8
        for (int m = 0; m < 64; m++) acc = fmaf(rs[m], oW[m * 64 + tid], acc);
        out_out[(size_t)b * OUTDIM + tid] = sigmoid_f(acc);
    }
}

// ---------------------------------------------------------------------------
extern "C" void kernel_launch(void* const* d_in, const int* in_sizes, int n_in,
                              void* d_out, int out_size)
{
    const float* x          = (const float*)d_in[0];
    const float* memory     = (const float*)d_in[1];
    const float* read_attn  = (const float*)d_in[2];
    const float* write_attn = (const float*)d_in[3];
    const float* cW         = (const float*)d_in[4];
    const float* cb         = (const float*)d_in[5];
    const float* oW         = (const float*)d_in[6];
    const float* ob         = (const float*)d_in[7];
    const float* whW        = (const float*)d_in[8];
    const float* whb        = (const float*)d_in[9];
    const float* weW        = (const float*)d_in[10];
    const float* web        = (const float*)d_in[11];
    const float* rhW        = (const float*)d_in[12];
    const float* rhb        = (const float*)d_in[13];

    float* out_out  = (float*)d_out;                               // (B,64)
    float* out_mem2 = out_out  + (size_t)BATCH * OUTDIM;           // (B,512,64)
    float* out_wr   = out_mem2 + (size_t)BATCH * NROWS * MDIM;     // (B,512)
    float* out_ww   = out_wr   + (size_t)BATCH * NROWS;            // (B,512)

    const size_t smemA = (size_t)(64 * INDIM + 64 * HDIM + 64 * 70 * 2) * sizeof(float);
    cudaFuncSetAttribute(ntm_params_kernel,
                         cudaFuncAttributeMaxDynamicSharedMemorySize, (int)smemA);

    ntm_params_kernel<<<BATCH / 64, 256, smemA>>>(x, cW, cb, whW, whb, weW, web, rhW, rhb);
    ntm_main_kernel<<<BATCH, 512>>>(memory, read_attn, write_attn, oW, ob,
                                    out_out, out_mem2, out_wr, out_ww);
}

// round 2
// speedup vs baseline: 1.8397x; 1.8397x over previous
#include <cuda_runtime.h>
#include <math.h>

#define BATCH  2048
#define NROWS  512
#define MDIM   64
#define HDIM   100
#define INDIM  64
#define OUTDIM 64
#define EPS    1e-8f

#define SCR_STRIDE 288
__device__ float g_scratch[(size_t)BATCH * SCR_STRIDE];
// composite weights: [64][268] then 268 bias (268 = 70 wh | 70 rh | 128 we)
#define WCOLS 268
__device__ float g_wcomp[64 * WCOLS + WCOLS];

__device__ __forceinline__ float softplus_f(float x) {
    return (x > 20.f) ? x : log1pf(expf(x));
}
__device__ __forceinline__ float sigmoid_f(float x) {
    return 1.f / (1.f + expf(-x));
}

__device__ __forceinline__ void cp_async16(float4* smem_dst, const float4* gmem_src) {
    unsigned s = (unsigned)__cvta_generic_to_shared(smem_dst);
    asm volatile("cp.async.cg.shared.global [%0], [%1], 16;\n" :: "r"(s), "l"(gmem_src));
}
#define CP_COMMIT() asm volatile("cp.async.commit_group;\n")

// ---------------------------------------------------------------------------
// Kernel 0: composite weights  W' = cW @ [whW|rhW|weW],  b' = cb@W + b
// ---------------------------------------------------------------------------
__global__ __launch_bounds__(256) void ntm_wcomp_kernel(
    const float* __restrict__ cW,  const float* __restrict__ cb,
    const float* __restrict__ whW, const float* __restrict__ whb,
    const float* __restrict__ weW, const float* __restrict__ web,
    const float* __restrict__ rhW, const float* __restrict__ rhb)
{
    int idx = blockIdx.x * 256 + threadIdx.x;
    if (idx < 64 * WCOLS) {
        int i = idx / WCOLS, j = idx % WCOLS;
        const float* row = cW + i * HDIM;
        float acc = 0.f;
        if (j < 70) {
            #pragma unroll 4
            for (int k = 0; k < HDIM; k++) acc = fmaf(row[k], whW[k * 70 + j], acc);
        } else if (j < 140) {
            int jj = j - 70;
            #pragma unroll 4
            for (int k = 0; k < HDIM; k++) acc = fmaf(row[k], rhW[k * 70 + jj], acc);
        } else {
            int jj = j - 140;
            #pragma unroll 4
            for (int k = 0; k < HDIM; k++) acc = fmaf(row[k], weW[k * 128 + jj], acc);
        }
        g_wcomp[idx] = acc;
    } else if (idx < 64 * WCOLS + WCOLS) {
        int j = idx - 64 * WCOLS;
        float acc;
        if (j < 70) {
            acc = whb[j];
            #pragma unroll 4
            for (int k = 0; k < HDIM; k++) acc = fmaf(cb[k], whW[k * 70 + j], acc);
        } else if (j < 140) {
            int jj = j - 70;
            acc = rhb[jj];
            #pragma unroll 4
            for (int k = 0; k < HDIM; k++) acc = fmaf(cb[k], rhW[k * 70 + jj], acc);
        } else {
            int jj = j - 140;
            acc = web[jj];
            #pragma unroll 4
            for (int k = 0; k < HDIM; k++) acc = fmaf(cb[k], weW[k * 128 + jj], acc);
        }
        g_wcomp[64 * WCOLS + j] = acc;
    }
}

// ---------------------------------------------------------------------------
// Kernel 1: per-batch head parameters via composite weights.
// grid 128 x 320 threads, 16 batches per CTA.
// scratch per batch: [0:64) k_w  [64:128) k_r  [128:192) e  [192:256) a
// [256..269]: beta_w,gate_w,sh_w0..2,gamma_w,kn_w, beta_r,gate_r,sh_r0..2,gamma_r,kn_r
// ---------------------------------------------------------------------------
__global__ __launch_bounds__(320) void ntm_params_kernel(const float* __restrict__ x)
{
    __shared__ float xs[64 * 20];     // [i][b], pad 20 (float4-aligned)
    __shared__ float ps[16 * WCOLS];  // [b][j]

    const int tid = threadIdx.x;
    const int b0  = blockIdx.x * 16;

    for (int idx = tid; idx < 16 * 64; idx += 320) {
        int b = idx >> 6, i = idx & 63;
        xs[i * 20 + b] = x[(size_t)(b0 + b) * 64 + i];
    }
    __syncthreads();

    if (tid < WCOLS) {
        const int j = tid;
        float acc[16];
        float bj = g_wcomp[64 * WCOLS + j];
        #pragma unroll
        for (int b = 0; b < 16; b++) acc[b] = bj;
        #pragma unroll 4
        for (int i = 0; i < 64; i++) {
            float w = g_wcomp[i * WCOLS + j];
            const float4* xv = (const float4*)(xs + i * 20);
            float4 x0 = xv[0], x1 = xv[1], x2 = xv[2], x3 = xv[3];
            acc[0]  = fmaf(x0.x, w, acc[0]);  acc[1]  = fmaf(x0.y, w, acc[1]);
            acc[2]  = fmaf(x0.z, w, acc[2]);  acc[3]  = fmaf(x0.w, w, acc[3]);
            acc[4]  = fmaf(x1.x, w, acc[4]);  acc[5]  = fmaf(x1.y, w, acc[5]);
            acc[6]  = fmaf(x1.z, w, acc[6]);  acc[7]  = fmaf(x1.w, w, acc[7]);
            acc[8]  = fmaf(x2.x, w, acc[8]);  acc[9]  = fmaf(x2.y, w, acc[9]);
            acc[10] = fmaf(x2.z, w, acc[10]); acc[11] = fmaf(x2.w, w, acc[11]);
            acc[12] = fmaf(x3.x, w, acc[12]); acc[13] = fmaf(x3.y, w, acc[13]);
            acc[14] = fmaf(x3.z, w, acc[14]); acc[15] = fmaf(x3.w, w, acc[15]);
        }
        #pragma unroll
        for (int b = 0; b < 16; b++) ps[b * WCOLS + j] = acc[b];
    }
    __syncthreads();

    // e / a  (we segment starts at 140)
    for (int idx = tid; idx < 16 * 128; idx += 320) {
        int b = idx >> 7, j = idx & 127;
        float v = ps[b * WCOLS + 140 + j];
        float* scr = g_scratch + (size_t)(b0 + b) * SCR_STRIDE;
        if (j < 64) scr[128 + j]        = sigmoid_f(v);
        else        scr[192 + (j - 64)] = v;
    }
    // k vectors
    for (int idx = tid; idx < 16 * 64; idx += 320) {
        int b = idx >> 6, j = idx & 63;
        float* scr = g_scratch + (size_t)(b0 + b) * SCR_STRIDE;
        scr[j]      = ps[b * WCOLS + j];
        scr[64 + j] = ps[b * WCOLS + 70 + j];
    }
    // scalars
    if (tid < 16) {
        const float* pw = ps + tid * WCOLS;
        const float* pr = pw + 70;
        float* scr = g_scratch + (size_t)(b0 + tid) * SCR_STRIDE + 256;
        float ssw = 0.f, ssr = 0.f;
        #pragma unroll 8
        for (int j = 0; j < 64; j++) { ssw = fmaf(pw[j], pw[j], ssw); ssr = fmaf(pr[j], pr[j], ssr); }

        scr[0] = softplus_f(pw[64]);
        scr[1] = sigmoid_f(pw[65]);
        float m  = fmaxf(pw[66], fmaxf(pw[67], pw[68]));
        float e0 = expf(pw[66] - m), e1 = expf(pw[67] - m), e2 = expf(pw[68] - m);
        float s  = e0 + e1 + e2;
        scr[2] = e0 / s; scr[3] = e1 / s; scr[4] = e2 / s;
        scr[5] = 1.f + softplus_f(pw[69]);
        scr[6] = fmaxf(sqrtf(ssw), EPS);

        scr[7] = softplus_f(pr[64]);
        scr[8] = sigmoid_f(pr[65]);
        m  = fmaxf(pr[66], fmaxf(pr[67], pr[68]));
        e0 = expf(pr[66] - m); e1 = expf(pr[67] - m); e2 = expf(pr[68] - m);
        s  = e0 + e1 + e2;
        scr[9] = e0 / s; scr[10] = e1 / s; scr[11] = e2 / s;
        scr[12] = 1.f + softplus_f(pr[69]);
        scr[13] = fmaxf(sqrtf(ssr), EPS);
    }
}

// ---------------------------------------------------------------------------
// Block reductions over 512 threads
// ---------------------------------------------------------------------------
__device__ __forceinline__ float blockReduceSum512(float v, float* red) {
    #pragma unroll
    for (int o = 16; o > 0; o >>= 1) v += __shfl_xor_sync(0xffffffffu, v, o);
    int warp = threadIdx.x >> 5, lane = threadIdx.x & 31;
    if (lane == 0) red[warp] = v;
    __syncthreads();
    if (threadIdx.x < 32) {
        v = (lane < 16) ? red[lane] : 0.f;
        #pragma unroll
        for (int o = 8; o > 0; o >>= 1) v += __shfl_xor_sync(0xffffffffu, v, o);
        if (lane == 0) red[0] = v;
    }
    __syncthreads();
    float r = red[0];
    __syncthreads();
    return r;
}
__device__ __forceinline__ float blockReduceMax512(float v, float* red) {
    #pragma unroll
    for (int o = 16; o > 0; o >>= 1) v = fmaxf(v, __shfl_xor_sync(0xffffffffu, v, o));
    int warp = threadIdx.x >> 5, lane = threadIdx.x & 31;
    if (lane == 0) red[warp] = v;
    __syncthreads();
    if (threadIdx.x < 32) {
        v = (lane < 16) ? red[lane] : -INFINITY;
        #pragma unroll
        for (int o = 8; o > 0; o >>= 1) v = fmaxf(v, __shfl_xor_sync(0xffffffffu, v, o));
        if (lane == 0) red[0] = v;
    }
    __syncthreads();
    float r = red[0];
    __syncthreads();
    return r;
}

// ---------------------------------------------------------------------------
// Kernel 2: main. One CTA per batch, 512 threads.
// Pass 1: cp.async double-buffered tiles (128 rows), swizzled smem, quad-split
//         moment computation -> mom[8][512].
// Addressing (write then read head; read head uses closed-form on virtual mem2).
// Pass 2: column-major coalesced mem2 write (+__stcs) + S1/S2 column sums.
// ---------------------------------------------------------------------------
// dynamic smem layout (floats):
//  [0,16384)      bufA/bufB (2 x 2048 float4)
//  [16384,20480)  part[8][512]   (reused as s1p/s2p in pass 2)
//  [20480,24576)  mom[8][512]
//  [24576..]      c_kw(64) c_kr(64) c_e(64) c_a(64) ww(512) wr(512) wg(512)
//                 red(16) scal(16) rs(64) sc2(2)
#define SMEM_FLOATS (16384 + 4096 + 4096 + 256 + 1536 + 16 + 16 + 64 + 16)

__global__ __launch_bounds__(512, 2) void ntm_main_kernel(
    const float* __restrict__ memory, const float* __restrict__ read_attn,
    const float* __restrict__ write_attn, const float* __restrict__ oW,
    const float* __restrict__ ob,
    float* __restrict__ out_out, float* __restrict__ out_mem2,
    float* __restrict__ out_wr,  float* __restrict__ out_ww)
{
    extern __shared__ float sm[];
    float4* bufA  = (float4*)sm;
    float4* bufB  = bufA + 2048;
    float*  part  = sm + 16384;
    float*  mom   = sm + 20480;
    float*  c_kw  = sm + 24576;
    float*  c_kr  = c_kw + 64;
    float*  c_e   = c_kr + 64;
    float*  c_a   = c_e  + 64;
    float*  ww_s  = c_a  + 64;
    float*  wr_s  = ww_s + 512;
    float*  wg_s  = wr_s + 512;
    float*  red   = wg_s + 512;
    float*  scal  = red  + 16;
    float*  rs    = scal + 16;
    float*  sc2   = rs   + 64;

    const int tid = threadIdx.x;
    const int b   = blockIdx.x;
    const float* mbase = memory + (size_t)b * NROWS * MDIM;

    // ---- prologue: start the DRAM stream immediately ----------------------
    {
        const float4* src = (const float4*)mbase;
        #pragma unroll
        for (int k = 0; k < 4; k++) {
            int f = tid + k * 512;
            int r = f >> 4, c4 = f & 15;
            cp_async16(&bufA[r * 16 + (c4 ^ (r & 15))], &src[f]);
        }
        CP_COMMIT();
        src += 2048;
        #pragma unroll
        for (int k = 0; k < 4; k++) {
            int f = tid + k * 512;
            int r = f >> 4, c4 = f & 15;
            cp_async16(&bufB[r * 16 + (c4 ^ (r & 15))], &src[f]);
        }
        CP_COMMIT();
    }

    // ---- coefficients ------------------------------------------------------
    {
        const float* scr = g_scratch + (size_t)b * SCR_STRIDE;
        if (tid < 64) {
            c_kw[tid] = scr[tid];
            c_kr[tid] = scr[64 + tid];
            c_e[tid]  = scr[128 + tid];
            c_a[tid]  = scr[192 + tid];
        } else if (tid < 80) {
            scal[tid - 64] = scr[256 + (tid - 64)];
        }
    }
    __syncthreads();
    if (tid < 32) {
        float ka = c_kr[tid] * c_a[tid] + c_kr[tid + 32] * c_a[tid + 32];
        float aa = c_a[tid]  * c_a[tid] + c_a[tid + 32]  * c_a[tid + 32];
        #pragma unroll
        for (int o = 16; o > 0; o >>= 1) {
            ka += __shfl_xor_sync(0xffffffffu, ka, o);
            aa += __shfl_xor_sync(0xffffffffu, aa, o);
        }
        if (tid == 0) { sc2[0] = ka; sc2[1] = aa; }
    }

    // ---- pass 1: tiles -----------------------------------------------------
    const int q = tid >> 7, r = tid & 127;
    const float4* kw4 = (const float4*)c_kw;
    const float4* kr4 = (const float4*)c_kr;
    const float4* e4  = (const float4*)c_e;
    const float4* a4  = (const float4*)c_a;

    #pragma unroll 1
    for (int tt = 0; tt < 4; tt++) {
        if (tt < 3) { asm volatile("cp.async.wait_group 1;\n"); }
        else        { asm volatile("cp.async.wait_group 0;\n"); }
        __syncthreads();

        const float4* bt = (tt & 1) ? bufB : bufA;
        float d0 = 0, q0 = 0, d1 = 0, d2 = 0, p1 = 0, p2 = 0, s1 = 0, s2 = 0;
        #pragma unroll
        for (int j = 0; j < 4; j++) {
            int c4 = (q << 2) + j;
            float4 v  = bt[r * 16 + (c4 ^ (r & 15))];
            float4 kw = kw4[c4], kr = kr4[c4], ee = e4[c4], aa4 = a4[c4];
            {
                float vv = v.x, ev = ee.x * vv;
                d0 = fmaf(kw.x, vv, d0);  d1 = fmaf(kr.x, vv, d1);  s1 = fmaf(aa4.x, vv, s1);
                q0 = fmaf(vv, vv, q0);    p1 = fmaf(vv, ev, p1);    p2 = fmaf(ev, ev, p2);
                d2 = fmaf(kr.x, ev, d2);  s2 = fmaf(aa4.x, ev, s2);
            }
            {
                float vv = v.y, ev = ee.y * vv;
                d0 = fmaf(kw.y, vv, d0);  d1 = fmaf(kr.y, vv, d1);  s1 = fmaf(aa4.y, vv, s1);
                q0 = fmaf(vv, vv, q0);    p1 = fmaf(vv, ev, p1);    p2 = fmaf(ev, ev, p2);
                d2 = fmaf(kr.y, ev, d2);  s2 = fmaf(aa4.y, ev, s2);
            }
            {
                float vv = v.z, ev = ee.z * vv;
                d0 = fmaf(kw.z, vv, d0);  d1 = fmaf(kr.z, vv, d1);  s1 = fmaf(aa4.z, vv, s1);
                q0 = fmaf(vv, vv, q0);    p1 = fmaf(vv, ev, p1);    p2 = fmaf(ev, ev, p2);
                d2 = fmaf(kr.z, ev, d2);  s2 = fmaf(aa4.z, ev, s2);
            }
            {
                float vv = v.w, ev = ee.w * vv;
                d0 = fmaf(kw.w, vv, d0);  d1 = fmaf(kr.w, vv, d1);  s1 = fmaf(aa4.w, vv, s1);
                q0 = fmaf(vv, vv, q0);    p1 = fmaf(vv, ev, p1);    p2 = fmaf(ev, ev, p2);
                d2 = fmaf(kr.w, ev, d2);  s2 = fmaf(aa4.w, ev, s2);
            }
        }
        part[0 * 512 + tid] = d0;  part[1 * 512 + tid] = q0;
        part[2 * 512 + tid] = d1;  part[3 * 512 + tid] = d2;
        part[4 * 512 + tid] = p1;  part[5 * 512 + tid] = p2;
        part[6 * 512 + tid] = s1;  part[7 * 512 + tid] = s2;
        __syncthreads();

        if (tt + 2 < 4) {  // refill the buffer we just consumed
            float4* dst = (tt & 1) ? bufB : bufA;
            const float4* src = (const float4*)(mbase + (size_t)(tt + 2) * 8192);
            #pragma unroll
            for (int k = 0; k < 4; k++) {
                int f = tid + k * 512;
                int rr = f >> 4, c4 = f & 15;
                cp_async16(&dst[rr * 16 + (c4 ^ (rr & 15))], &src[f]);
            }
            CP_COMMIT();
        }
        if (tid < 128) {
            int n = tt * 128 + tid;
            #pragma unroll
            for (int m = 0; m < 8; m++) {
                float s = part[m * 512 + tid] + part[m * 512 + 128 + tid]
                        + part[m * 512 + 256 + tid] + part[m * 512 + 384 + tid];
                mom[m * 512 + n] = s;
            }
        }
    }
    __syncthreads();

    // ---- addressing --------------------------------------------------------
    const int n = tid;
    const float d0 = mom[n],            q0 = mom[512 + n];
    const float d1 = mom[1024 + n],     d2 = mom[1536 + n];
    const float p1 = mom[2048 + n],     p2 = mom[2560 + n];
    const float t1 = mom[3072 + n],     t2 = mom[3584 + n];

    const float beta_w = scal[0], gate_w = scal[1], shw0 = scal[2], shw1 = scal[3],
                shw2 = scal[4], gamma_w = scal[5], kn_w = scal[6];
    const float beta_r = scal[7], gate_r = scal[8], shr0 = scal[9], shr1 = scal[10],
                shr2 = scal[11], gamma_r = scal[12], kn_r = scal[13];
    const float ka = sc2[0], aa = sc2[1];

    // write head
    float mn = fmaxf(sqrtf(q0), EPS);
    float sw = beta_w * d0 / (kn_w * mn);
    float mx  = blockReduceMax512(sw, red);
    float ex  = expf(sw - mx);
    float sum = blockReduceSum512(ex, red);
    float wc  = ex / sum;
    float wgv = gate_w * wc + (1.f - gate_w) * write_attn[(size_t)b * NROWS + n];
    wg_s[n] = wgv;
    __syncthreads();
    float tw  = shw2 * wg_s[(n + 511) & 511] + shw1 * wgv + shw0 * wg_s[(n + 1) & 511];
    float twg = powf(tw, gamma_w);
    float tsum = blockReduceSum512(twg, red);
    float ww = twg / (EPS + tsum);
    ww_s[n] = ww;
    out_ww[(size_t)b * NROWS + n] = ww;

    // read head on virtual mem2
    float dot2 = d1 - ww * d2 + ww * ka;
    float ss2  = q0 - 2.f * ww * p1 + ww * ww * p2
               + 2.f * ww * t1 - 2.f * ww * ww * t2 + ww * ww * aa;
    float mn2 = fmaxf(sqrtf(fmaxf(ss2, 0.f)), EPS);
    float sr  = beta_r * dot2 / (kn_r * mn2);
    mx  = blockReduceMax512(sr, red);
    ex  = expf(sr - mx);
    sum = blockReduceSum512(ex, red);
    wc  = ex / sum;
    float wgv2 = gate_r * wc + (1.f - gate_r) * read_attn[(size_t)b * NROWS + n];
    wg_s[n] = wgv2;
    __syncthreads();
    float tw2  = shr2 * wg_s[(n + 511) & 511] + shr1 * wgv2 + shr0 * wg_s[(n + 1) & 511];
    float twg2 = powf(tw2, gamma_r);
    float tsum2 = blockReduceSum512(twg2, red);
    float wr = twg2 / (EPS + tsum2);
    wr_s[n] = wr;
    out_wr[(size_t)b * NROWS + n] = wr;

    float cwr = blockReduceSum512(wr * ww, red);  // also syncs ww_s/wr_s

    // ---- pass 2: mem2 + S1/S2 ----------------------------------------------
    float* s1p = part;          // reuse
    float* s2p = part + 512;
    {
        const int m = tid & 63, g = tid >> 6;
        const float em = c_e[m], am = c_a[m];
        float*       m2b = out_mem2 + (size_t)b * NROWS * MDIM;
        float s1 = 0.f, s2 = 0.f;
        #pragma unroll 4
        for (int i = 0; i < 64; i++) {
            int nn = (g << 6) + i;
            float wwn = ww_s[nn], wrn = wr_s[nn];
            float v = __ldg(mbase + nn * 64 + m);
            float m2 = fmaf(v, 1.f - wwn * em, wwn * am);
            __stcs(m2b + nn * 64 + m, m2);
            s1 = fmaf(wrn, v, s1);
            s2 = fmaf(wrn * wwn, v, s2);
        }
        s1p[tid] = s1;  s2p[tid] = s2;
    }
    __syncthreads();

    if (tid < 64) {
        float r1 = 0.f, r2 = 0.f;
        #pragma unroll
        for (int g = 0; g < 8; g++) { r1 += s1p[g * 64 + tid]; r2 += s2p[g * 64 + tid]; }
        rs[tid] = r1 - c_e[tid] * r2 + cwr * c_a[tid];
    }
    __syncthreads();

    if (tid < 64) {
        float acc = ob[tid];
        #pragma unroll 8
        for (int m = 0; m < 64; m++) acc = fmaf(rs[m], oW[m * 64 + tid], acc);
        out_out[(size_t)b * OUTDIM + tid] = sigmoid_f(acc);
    }
}

// ---------------------------------------------------------------------------
extern "C" void kernel_launch(void* const* d_in, const int* in_sizes, int n_in,
                              void* d_out, int out_size)
{
    const float* x          = (const float*)d_in[0];
    const float* memory     = (const float*)d_in[1];
    const float* read_attn  = (const float*)d_in[2];
    const float* write_attn = (const float*)d_in[3];
    const float* cW         = (const float*)d_in[4];
    const float* cb         = (const float*)d_in[5];
    const float* oW         = (const float*)d_in[6];
    const float* ob         = (const float*)d_in[7];
    const float* whW        = (const float*)d_in[8];
    const float* whb        = (const float*)d_in[9];
    const float* weW        = (const float*)d_in[10];
    const float* web        = (const float*)d_in[11];
    const float* rhW        = (const float*)d_in[12];
    const float* rhb        = (const float*)d_in[13];

    float* out_out  = (float*)d_out;
    float* out_mem2 = out_out  + (size_t)BATCH * OUTDIM;
    float* out_wr   = out_mem2 + (size_t)BATCH * NROWS * MDIM;
    float* out_ww   = out_wr   + (size_t)BATCH * NROWS;

    const int smemB = SMEM_FLOATS * (int)sizeof(float);
    static int configured = 0;
    cudaFuncSetAttribute(ntm_main_kernel,
                         cudaFuncAttributeMaxDynamicSharedMemorySize, smemB);
    (void)configured;

    ntm_wcomp_kernel<<<(64 * WCOLS + WCOLS + 255) / 256, 256>>>(
        cW, cb, whW, whb, weW, web, rhW, rhb);
    ntm_params_kernel<<<BATCH / 16, 320>>>(x);
    ntm_main_kernel<<<BATCH, 512, smemB>>>(memory, read_attn, write_attn, oW, ob,
                                           out_out, out_mem2, out_wr, out_ww);
}